// round 7
// baseline (speedup 1.0000x reference)
#include <cuda_runtime.h>
#include <cuda_bf16.h>
#include <math.h>

#define TOK 32768
#define DMODEL 256
#define HFF 1024
#define QKVD 768
#define PK 768

// ---------------- scratch (no allocs allowed) ----------------
__device__ float g_patches[TOK * PK];
__device__ float g_pre[TOK * DMODEL];
__device__ float g_h0[TOK * DMODEL];
__device__ float g_hid[TOK * HFF];
__device__ float g_tmp[TOK * DMODEL];
__device__ float g_qkv[TOK * QKVD];
__device__ float g_h2[TOK * DMODEL];

// ---------------- im2col: x(32,3,512,512) -> patches(32768,768) ----------------
__global__ void im2col_kernel(const float* __restrict__ x) {
    int idx = blockIdx.x * blockDim.x + threadIdx.x;  // one float4; total TOK*192 exact
    int tok = idx / 192;
    int p4  = (idx % 192) * 4;
    int b = tok >> 10;
    int n = tok & 1023;
    int ph = n >> 5, pw = n & 31;
    int c = p4 >> 8;
    int r = p4 & 255;
    int py = r >> 4, px = r & 15;
    const float* src = x + (((size_t)(b * 3 + c) * 512 + ph * 16 + py) * 512 + pw * 16 + px);
    float4 v = *(const float4*)src;
    *(float4*)(g_patches + (size_t)tok * PK + p4) = v;
}

// ---------------- LayerNorm + sinusoidal PE (reads g_pre, writes g_h0) ----------------
__global__ void ln_pe_kernel(const float* __restrict__ w, const float* __restrict__ b) {
    int gt = blockIdx.x * 8 + (threadIdx.x >> 5);   // token
    int lane = threadIdx.x & 31;
    const float4* row = (const float4*)(g_pre + (size_t)gt * DMODEL);
    float4 v0 = row[lane];
    float4 v1 = row[lane + 32];
    float s  = v0.x + v0.y + v0.z + v0.w + v1.x + v1.y + v1.z + v1.w;
    float ss = v0.x*v0.x + v0.y*v0.y + v0.z*v0.z + v0.w*v0.w
             + v1.x*v1.x + v1.y*v1.y + v1.z*v1.z + v1.w*v1.w;
    #pragma unroll
    for (int off = 16; off >= 1; off >>= 1) {
        s  += __shfl_xor_sync(0xffffffffu, s, off);
        ss += __shfl_xor_sync(0xffffffffu, ss, off);
    }
    float mean = s * (1.0f / 256.0f);
    float var  = ss * (1.0f / 256.0f) - mean * mean;
    float rstd = rsqrtf(var + 1e-5f);
    int n = gt & 1023;
    float nf = (float)n;

    float4 wv0 = ((const float4*)w)[lane];
    float4 wv1 = ((const float4*)w)[lane + 32];
    float4 bv0 = ((const float4*)b)[lane];
    float4 bv1 = ((const float4*)b)[lane + 32];

    float4 o0, o1;
    int d0 = lane * 4;
    int d1 = 128 + lane * 4;
    const float C = -9.210340371976184f / 256.0f;   // -ln(10000)/256
    #pragma unroll
    for (int i = 0; i < 8; i++) {
        int d = (i < 4) ? (d0 + i) : (d1 + (i - 4));
        float xv = (i == 0) ? v0.x : (i == 1) ? v0.y : (i == 2) ? v0.z : (i == 3) ? v0.w
                 : (i == 4) ? v1.x : (i == 5) ? v1.y : (i == 6) ? v1.z : v1.w;
        float wv = (i == 0) ? wv0.x : (i == 1) ? wv0.y : (i == 2) ? wv0.z : (i == 3) ? wv0.w
                 : (i == 4) ? wv1.x : (i == 5) ? wv1.y : (i == 6) ? wv1.z : wv1.w;
        float bv = (i == 0) ? bv0.x : (i == 1) ? bv0.y : (i == 2) ? bv0.z : (i == 3) ? bv0.w
                 : (i == 4) ? bv1.x : (i == 5) ? bv1.y : (i == 6) ? bv1.z : bv1.w;
        float ang = nf * expf(C * (float)(d & ~1));
        float pe = (d & 1) ? cosf(ang) : sinf(ang);
        float o = (xv - mean) * rstd * wv + bv + pe;
        if      (i == 0) o0.x = o; else if (i == 1) o0.y = o; else if (i == 2) o0.z = o; else if (i == 3) o0.w = o;
        else if (i == 4) o1.x = o; else if (i == 5) o1.y = o; else if (i == 6) o1.z = o; else o1.w = o;
    }
    float4* orow = (float4*)(g_h0 + (size_t)gt * DMODEL);
    orow[lane]      = o0;
    orow[lane + 32] = o1;
}

// ---------------- helpers ----------------
__device__ __forceinline__ float gelu_f(float x) {
    return 0.5f * x * (1.0f + tanhf(0.7978845608028654f * (x + 0.044715f * x * x * x)));
}

__device__ __forceinline__ void mma_bf16(float* d, const unsigned* a, const unsigned* b) {
    asm volatile(
        "mma.sync.aligned.m16n8k16.row.col.f32.bf16.bf16.f32 "
        "{%0,%1,%2,%3}, {%4,%5,%6,%7}, {%8,%9}, {%0,%1,%2,%3};\n"
        : "+f"(d[0]), "+f"(d[1]), "+f"(d[2]), "+f"(d[3])
        : "r"(a[0]), "r"(a[1]), "r"(a[2]), "r"(a[3]), "r"(b[0]), "r"(b[1]));
}

#define LDSM4(r0, r1, r2, r3, addr) \
    asm volatile("ldmatrix.sync.aligned.m8n8.x4.shared.b16 {%0,%1,%2,%3}, [%4];" \
                 : "=r"(r0), "=r"(r1), "=r"(r2), "=r"(r3) : "r"(addr))

// split 8 consecutive fp32 into hi/lo bf16 pair-packed words
__device__ __forceinline__ void split2_pack(const float* v, unsigned* hi, unsigned* lo) {
    #pragma unroll
    for (int i = 0; i < 4; i++) {
        __nv_bfloat16 h0 = __float2bfloat16_rn(v[2*i]);
        __nv_bfloat16 h1 = __float2bfloat16_rn(v[2*i+1]);
        __nv_bfloat16 l0 = __float2bfloat16_rn(v[2*i]   - __bfloat162float(h0));
        __nv_bfloat16 l1 = __float2bfloat16_rn(v[2*i+1] - __bfloat162float(h1));
        __nv_bfloat162 hp = __halves2bfloat162(h0, h1);   // x = low = even k
        __nv_bfloat162 lp = __halves2bfloat162(l0, l1);
        hi[i] = *(unsigned*)&hp;
        lo[i] = *(unsigned*)&lp;
    }
}

// ---------------- 3xBF16 tensor-core GEMM with ldmatrix ----------------
// C[M,N] = A[M,K] @ B[N,K]^T. Block tile 128x128, Ktile=16, double-buffered,
// ONE sync per K-tile. 8 warps in 2(m) x 4(n), warp tile 64x32.
// smem: per buffer 4 planes (Ahi, Alo, Bhi, Blo), each row-major [128][16]bf16
// with 48-byte row stride (12 words: 8 data + 4 pad -> conflict-free ldmatrix
// phases AND conflict-free STS.128).
#define ROWSTRIDE_W 12
#define ROWSTRIDE_B 48
#define PLANE_W (128 * ROWSTRIDE_W)      // 1536 words
#define PLANE_B (PLANE_W * 4)            // 6144 bytes
#define BUF_W (4 * PLANE_W)              // 6144 words
#define BUF_B (BUF_W * 4)                // 24576 bytes
#define GEMM_SMEM_BYTES (2 * BUF_B)      // 49152 bytes (= default 48KB limit)

__device__ __forceinline__ void cvt_store_tile(unsigned* buf, int word_off,
                                               const float4& av0, const float4& av1,
                                               const float4& bv0, const float4& bv1) {
    float va[8] = {av0.x, av0.y, av0.z, av0.w, av1.x, av1.y, av1.z, av1.w};
    float vb[8] = {bv0.x, bv0.y, bv0.z, bv0.w, bv1.x, bv1.y, bv1.z, bv1.w};
    unsigned ahi[4], alo[4], bhi[4], blo[4];
    split2_pack(va, ahi, alo);
    split2_pack(vb, bhi, blo);
    *(uint4*)(buf + word_off)               = make_uint4(ahi[0], ahi[1], ahi[2], ahi[3]);
    *(uint4*)(buf + PLANE_W + word_off)     = make_uint4(alo[0], alo[1], alo[2], alo[3]);
    *(uint4*)(buf + 2 * PLANE_W + word_off) = make_uint4(bhi[0], bhi[1], bhi[2], bhi[3]);
    *(uint4*)(buf + 3 * PLANE_W + word_off) = make_uint4(blo[0], blo[1], blo[2], blo[3]);
}

template <bool GELU>
__global__ __launch_bounds__(256, 2)
void mp_gemm(const float* __restrict__ A, const float* __restrict__ Bm,
             const float* __restrict__ bias, const float* __restrict__ res,
             float* __restrict__ C, int M, int N, int K) {
    extern __shared__ unsigned sm[];
    unsigned sbase = (unsigned)__cvta_generic_to_shared(sm);

    int t = threadIdx.x;
    int warp = t >> 5, lane = t & 31;
    int g = lane >> 2, t4 = lane & 3;
    int wm = (warp >> 2) * 64;   // warp m-offset
    int wn = (warp & 3) * 32;    // warp n-offset
    int bx = blockIdx.x, by = blockIdx.y;

    // loader mapping: thread owns 8 consecutive k of one row
    int lrow = t & 127;
    int half = t >> 7;           // k-half: 0 -> k0-7, 1 -> k8-15
    int lk   = half * 8;
    const float* Ag = A  + (size_t)(by * 128 + lrow) * K + lk;
    const float* Bg = Bm + (size_t)(bx * 128 + lrow) * K + lk;
    int st_off = lrow * ROWSTRIDE_W + half * 4;   // word offset for STS.128

    // ldmatrix per-lane byte offsets (within a plane)
    // A tile mt: row = wm + mt*16 + (lane&7) + ((lane>>3)&1)*8, koff = (lane>>4)*16B
    unsigned a_off = (unsigned)((wm + (lane & 7) + ((lane >> 3) & 1) * 8) * ROWSTRIDE_B
                                + (lane >> 4) * 16);
    // B pair p (covers nt=2p, 2p+1): row = wn + (lane>>4)*8 + (lane&7) (+ p*16),
    // koff = ((lane>>3)&1)*16B
    unsigned b_off = (unsigned)((wn + (lane >> 4) * 8 + (lane & 7)) * ROWSTRIDE_B
                                + ((lane >> 3) & 1) * 16);

    float acc[4][4][4];
    #pragma unroll
    for (int i = 0; i < 4; i++)
        #pragma unroll
        for (int j = 0; j < 4; j++)
            #pragma unroll
            for (int c = 0; c < 4; c++) acc[i][j][c] = 0.0f;

    // prologue: tile 0 -> buffer 0
    float4 av0 = *(const float4*)(Ag);
    float4 av1 = *(const float4*)(Ag + 4);
    float4 bv0 = *(const float4*)(Bg);
    float4 bv1 = *(const float4*)(Bg + 4);
    cvt_store_tile(sm, st_off, av0, av1, bv0, bv1);
    __syncthreads();

    int ntiles = K >> 4;
    int buf = 0;
    for (int it = 0; it < ntiles; it++) {
        bool more = (it + 1 < ntiles);

        // global prefetch for next tile (latency hidden under mma)
        if (more) {
            int kn = (it + 1) << 4;
            av0 = *(const float4*)(Ag + kn);
            av1 = *(const float4*)(Ag + kn + 4);
            bv0 = *(const float4*)(Bg + kn);
            bv1 = *(const float4*)(Bg + kn + 4);
        }

        unsigned ab = sbase + buf * BUF_B;

        unsigned ah[4][4], al[4][4];
        #pragma unroll
        for (int mt = 0; mt < 4; mt++) {
            unsigned ad = ab + a_off + mt * (16 * ROWSTRIDE_B);
            LDSM4(ah[mt][0], ah[mt][1], ah[mt][2], ah[mt][3], ad);
            LDSM4(al[mt][0], al[mt][1], al[mt][2], al[mt][3], ad + PLANE_B);
        }
        unsigned bh[2][4], bl[2][4];
        #pragma unroll
        for (int p = 0; p < 2; p++) {
            unsigned bd = ab + 2 * PLANE_B + b_off + p * (16 * ROWSTRIDE_B);
            LDSM4(bh[p][0], bh[p][1], bh[p][2], bh[p][3], bd);
            LDSM4(bl[p][0], bl[p][1], bl[p][2], bl[p][3], bd + PLANE_B);
        }

        #pragma unroll
        for (int mt = 0; mt < 4; mt++)
            #pragma unroll
            for (int nt = 0; nt < 4; nt++) {
                int p = nt >> 1, q = nt & 1;
                unsigned bfh[2] = {bh[p][q * 2], bh[p][q * 2 + 1]};
                unsigned bfl[2] = {bl[p][q * 2], bl[p][q * 2 + 1]};
                mma_bf16(acc[mt][nt], ah[mt], bfh);
                mma_bf16(acc[mt][nt], ah[mt], bfl);
                mma_bf16(acc[mt][nt], al[mt], bfh);
            }

        // convert + store next tile into the other buffer, then single barrier
        if (more) {
            cvt_store_tile(sm + (buf ^ 1) * BUF_W, st_off, av0, av1, bv0, bv1);
            __syncthreads();
        }
        buf ^= 1;
    }

    // epilogue: c0,c1 -> (row, col..col+1); c2,c3 -> (row+8, col..col+1)
    #pragma unroll
    for (int mt = 0; mt < 4; mt++) {
        int row0 = by * 128 + wm + mt * 16 + g;
        #pragma unroll
        for (int nt = 0; nt < 4; nt++) {
            int col = bx * 128 + wn + nt * 8 + t4 * 2;
            float bx0 = 0.0f, bx1 = 0.0f;
            if (bias) { bx0 = bias[col]; bx1 = bias[col + 1]; }
            #pragma unroll
            for (int hh = 0; hh < 2; hh++) {
                int row = row0 + hh * 8;
                float v0 = acc[mt][nt][hh * 2 + 0] + bx0;
                float v1 = acc[mt][nt][hh * 2 + 1] + bx1;
                if (GELU) { v0 = gelu_f(v0); v1 = gelu_f(v1); }
                size_t off = (size_t)row * N + col;
                if (res) {
                    float2 rv = *(const float2*)(res + off);
                    v0 += rv.x; v1 += rv.y;
                }
                *(float2*)(C + off) = make_float2(v0, v1);
            }
        }
    }
}

// ---------------- windowed attention: one block per (batch, window, head) ----------------
__global__ __launch_bounds__(256)
void attn_kernel(const float* __restrict__ qkv, float* __restrict__ out) {
    __shared__ float Qs[64][36], Ks[64][36], Vs[64][36];
    __shared__ float Ps[64][65];
    int blk = blockIdx.x;
    int h = blk & 7, wwin = (blk >> 3) & 15, b = blk >> 7;
    int base = b * 1024 + wwin * 64;
    int t = threadIdx.x;

    for (int i = t; i < 512; i += 256) {
        int row = i >> 3, dg = (i & 7) * 4;
        const float* src = qkv + (size_t)(base + row) * QKVD + h * 32 + dg;
        float4 q4 = *(const float4*)(src);
        float4 k4 = *(const float4*)(src + 256);
        float4 v4 = *(const float4*)(src + 512);
        *(float4*)&Qs[row][dg] = q4;
        *(float4*)&Ks[row][dg] = k4;
        *(float4*)&Vs[row][dg] = v4;
    }
    __syncthreads();

    int qt  = (t >> 4) * 4;
    int kt4 = (t & 15) * 4;
    float s[4][4];
    #pragma unroll
    for (int i = 0; i < 4; i++)
        #pragma unroll
        for (int j = 0; j < 4; j++) s[i][j] = 0.0f;

    #pragma unroll
    for (int d = 0; d < 32; d += 4) {
        float4 qv[4], kv[4];
        #pragma unroll
        for (int i = 0; i < 4; i++) qv[i] = *(const float4*)&Qs[qt + i][d];
        #pragma unroll
        for (int j = 0; j < 4; j++) kv[j] = *(const float4*)&Ks[kt4 + j][d];
        #pragma unroll
        for (int i = 0; i < 4; i++)
            #pragma unroll
            for (int j = 0; j < 4; j++)
                s[i][j] += qv[i].x * kv[j].x + qv[i].y * kv[j].y +
                           qv[i].z * kv[j].z + qv[i].w * kv[j].w;
    }
    const float scale = 0.17677669529663687f;  // 1/sqrt(32)
    #pragma unroll
    for (int i = 0; i < 4; i++) {
        #pragma unroll
        for (int j = 0; j < 4; j++) s[i][j] *= scale;
        float m = fmaxf(fmaxf(s[i][0], s[i][1]), fmaxf(s[i][2], s[i][3]));
        #pragma unroll
        for (int off = 8; off >= 1; off >>= 1)
            m = fmaxf(m, __shfl_xor_sync(0xffffffffu, m, off));
        float sum = 0.0f;
        #pragma unroll
        for (int j = 0; j < 4; j++) { s[i][j] = expf(s[i][j] - m); sum += s[i][j]; }
        #pragma unroll
        for (int off = 8; off >= 1; off >>= 1)
            sum += __shfl_xor_sync(0xffffffffu, sum, off);
        float inv = 1.0f / sum;
        #pragma unroll
        for (int j = 0; j < 4; j++) Ps[qt + i][kt4 + j] = s[i][j] * inv;
    }
    __syncthreads();

    int q = t >> 2, d0 = (t & 3) * 8;
    float acc[8];
    #pragma unroll
    for (int j = 0; j < 8; j++) acc[j] = 0.0f;
    #pragma unroll 4
    for (int k = 0; k < 64; k++) {
        float p = Ps[q][k];
        float4 v0 = *(const float4*)&Vs[k][d0];
        float4 v1 = *(const float4*)&Vs[k][d0 + 4];
        acc[0] += p * v0.x; acc[1] += p * v0.y; acc[2] += p * v0.z; acc[3] += p * v0.w;
        acc[4] += p * v1.x; acc[5] += p * v1.y; acc[6] += p * v1.z; acc[7] += p * v1.w;
    }
    float* dst = out + (size_t)(base + q) * DMODEL + h * 32 + d0;
    *(float4*)(dst)     = make_float4(acc[0], acc[1], acc[2], acc[3]);
    *(float4*)(dst + 4) = make_float4(acc[4], acc[5], acc[6], acc[7]);
}

// ---------------- launch ----------------
extern "C" void kernel_launch(void* const* d_in, const int* in_sizes, int n_in,
                              void* d_out, int out_size) {
    (void)in_sizes; (void)n_in; (void)out_size;
    const float* x      = (const float*)d_in[0];
    const float* conv_w = (const float*)d_in[1];
    const float* conv_b = (const float*)d_in[2];
    const float* ln_w   = (const float*)d_in[3];
    const float* ln_b   = (const float*)d_in[4];
    const float* qkv_w  = (const float*)d_in[5];
    const float* qkv_b  = (const float*)d_in[6];
    const float* proj_w = (const float*)d_in[7];
    const float* proj_b = (const float*)d_in[8];
    const float* ff_w1  = (const float*)d_in[9];
    const float* ff_b1  = (const float*)d_in[10];
    const float* ff_w2  = (const float*)d_in[11];
    const float* ff_b2  = (const float*)d_in[12];
    float* out = (float*)d_out;

    float *patches, *pre, *h0, *hid, *tmp, *qkvp, *h2;
    cudaGetSymbolAddress((void**)&patches, g_patches);
    cudaGetSymbolAddress((void**)&pre,     g_pre);
    cudaGetSymbolAddress((void**)&h0,      g_h0);
    cudaGetSymbolAddress((void**)&hid,     g_hid);
    cudaGetSymbolAddress((void**)&tmp,     g_tmp);
    cudaGetSymbolAddress((void**)&qkvp,    g_qkv);
    cudaGetSymbolAddress((void**)&h2,      g_h2);

    // 1) patch extraction + embed GEMM + LN + PE
    im2col_kernel<<<24576, 256>>>(x);
    mp_gemm<false><<<dim3(2, 256), 256, GEMM_SMEM_BYTES>>>(patches, conv_w, conv_b, nullptr, pre, TOK, DMODEL, PK);
    ln_pe_kernel<<<4096, 256>>>(ln_w, ln_b);

    // 2) FFN #1
    mp_gemm<true ><<<dim3(8, 256), 256, GEMM_SMEM_BYTES>>>(h0,  ff_w1, ff_b1, nullptr, hid, TOK, HFF, DMODEL);
    mp_gemm<false><<<dim3(2, 256), 256, GEMM_SMEM_BYTES>>>(hid, ff_w2, ff_b2, nullptr, tmp, TOK, DMODEL, HFF);

    // 3) windowed attention (qkv -> attn -> proj + residual(h0))
    mp_gemm<false><<<dim3(6, 256), 256, GEMM_SMEM_BYTES>>>(tmp, qkv_w, qkv_b, nullptr, qkvp, TOK, QKVD, DMODEL);
    attn_kernel<<<4096, 256>>>(qkvp, tmp);
    mp_gemm<false><<<dim3(2, 256), 256, GEMM_SMEM_BYTES>>>(tmp, proj_w, proj_b, h0, h2, TOK, DMODEL, DMODEL);

    // 4) FFN #2 + residual(h2) -> d_out
    mp_gemm<true ><<<dim3(8, 256), 256, GEMM_SMEM_BYTES>>>(h2,  ff_w1, ff_b1, nullptr, hid, TOK, HFF, DMODEL);
    mp_gemm<false><<<dim3(2, 256), 256, GEMM_SMEM_BYTES>>>(hid, ff_w2, ff_b2, h2, out, TOK, DMODEL, HFF);
}

// round 8
// speedup vs baseline: 1.1983x; 1.1983x over previous
#include <cuda_runtime.h>
#include <cuda_bf16.h>
#include <math.h>

#define TOK 32768
#define DMODEL 256
#define HFF 1024
#define QKVD 768
#define PK 768

// ---------------- scratch (no allocs allowed) ----------------
__device__ float g_patches[TOK * PK];
__device__ float g_pre[TOK * DMODEL];
__device__ float g_h0[TOK * DMODEL];
__device__ float g_hid[TOK * HFF];
__device__ float g_tmp[TOK * DMODEL];
__device__ float g_qkv[TOK * QKVD];
__device__ float g_h2[TOK * DMODEL];

// pre-packed weight fragments: uint4 {b0hi,b1hi,b0lo,b1lo} per (nb,kt,lane)
// sizes (uint4) = N*K/4
#define OFF_CONV 0
#define OFF_QKV  49152
#define OFF_PROJ 98304
#define OFF_FF1  114688
#define OFF_FF2  180224
__device__ uint4 g_wpool[245760];

// ---------------- im2col: x(32,3,512,512) -> patches(32768,768) ----------------
__global__ void im2col_kernel(const float* __restrict__ x) {
    int idx = blockIdx.x * blockDim.x + threadIdx.x;  // one float4; total TOK*192 exact
    int tok = idx / 192;
    int p4  = (idx % 192) * 4;
    int b = tok >> 10;
    int n = tok & 1023;
    int ph = n >> 5, pw = n & 31;
    int c = p4 >> 8;
    int r = p4 & 255;
    int py = r >> 4, px = r & 15;
    const float* src = x + (((size_t)(b * 3 + c) * 512 + ph * 16 + py) * 512 + pw * 16 + px);
    float4 v = *(const float4*)src;
    *(float4*)(g_patches + (size_t)tok * PK + p4) = v;
}

// ---------------- LayerNorm + sinusoidal PE (reads g_pre, writes g_h0) ----------------
__global__ void ln_pe_kernel(const float* __restrict__ w, const float* __restrict__ b) {
    int gt = blockIdx.x * 8 + (threadIdx.x >> 5);   // token
    int lane = threadIdx.x & 31;
    const float4* row = (const float4*)(g_pre + (size_t)gt * DMODEL);
    float4 v0 = row[lane];
    float4 v1 = row[lane + 32];
    float s  = v0.x + v0.y + v0.z + v0.w + v1.x + v1.y + v1.z + v1.w;
    float ss = v0.x*v0.x + v0.y*v0.y + v0.z*v0.z + v0.w*v0.w
             + v1.x*v1.x + v1.y*v1.y + v1.z*v1.z + v1.w*v1.w;
    #pragma unroll
    for (int off = 16; off >= 1; off >>= 1) {
        s  += __shfl_xor_sync(0xffffffffu, s, off);
        ss += __shfl_xor_sync(0xffffffffu, ss, off);
    }
    float mean = s * (1.0f / 256.0f);
    float var  = ss * (1.0f / 256.0f) - mean * mean;
    float rstd = rsqrtf(var + 1e-5f);
    int n = gt & 1023;
    float nf = (float)n;

    float4 wv0 = ((const float4*)w)[lane];
    float4 wv1 = ((const float4*)w)[lane + 32];
    float4 bv0 = ((const float4*)b)[lane];
    float4 bv1 = ((const float4*)b)[lane + 32];

    float4 o0, o1;
    int d0 = lane * 4;
    int d1 = 128 + lane * 4;
    const float C = -9.210340371976184f / 256.0f;   // -ln(10000)/256
    #pragma unroll
    for (int i = 0; i < 8; i++) {
        int d = (i < 4) ? (d0 + i) : (d1 + (i - 4));
        float xv = (i == 0) ? v0.x : (i == 1) ? v0.y : (i == 2) ? v0.z : (i == 3) ? v0.w
                 : (i == 4) ? v1.x : (i == 5) ? v1.y : (i == 6) ? v1.z : v1.w;
        float wv = (i == 0) ? wv0.x : (i == 1) ? wv0.y : (i == 2) ? wv0.z : (i == 3) ? wv0.w
                 : (i == 4) ? wv1.x : (i == 5) ? wv1.y : (i == 6) ? wv1.z : wv1.w;
        float bv = (i == 0) ? bv0.x : (i == 1) ? bv0.y : (i == 2) ? bv0.z : (i == 3) ? bv0.w
                 : (i == 4) ? bv1.x : (i == 5) ? bv1.y : (i == 6) ? bv1.z : bv1.w;
        float ang = nf * expf(C * (float)(d & ~1));
        float pe = (d & 1) ? cosf(ang) : sinf(ang);
        float o = (xv - mean) * rstd * wv + bv + pe;
        if      (i == 0) o0.x = o; else if (i == 1) o0.y = o; else if (i == 2) o0.z = o; else if (i == 3) o0.w = o;
        else if (i == 4) o1.x = o; else if (i == 5) o1.y = o; else if (i == 6) o1.z = o; else o1.w = o;
    }
    float4* orow = (float4*)(g_h0 + (size_t)gt * DMODEL);
    orow[lane]      = o0;
    orow[lane + 32] = o1;
}

// ---------------- helpers ----------------
__device__ __forceinline__ float gelu_f(float x) {
    return 0.5f * x * (1.0f + tanhf(0.7978845608028654f * (x + 0.044715f * x * x * x)));
}

__device__ __forceinline__ void mma_bf16(float* d, const unsigned* a, const unsigned* b) {
    asm volatile(
        "mma.sync.aligned.m16n8k16.row.col.f32.bf16.bf16.f32 "
        "{%0,%1,%2,%3}, {%4,%5,%6,%7}, {%8,%9}, {%0,%1,%2,%3};\n"
        : "+f"(d[0]), "+f"(d[1]), "+f"(d[2]), "+f"(d[3])
        : "r"(a[0]), "r"(a[1]), "r"(a[2]), "r"(a[3]), "r"(b[0]), "r"(b[1]));
}

#define LDSM4(r0, r1, r2, r3, addr) \
    asm volatile("ldmatrix.sync.aligned.m8n8.x4.shared.b16 {%0,%1,%2,%3}, [%4];" \
                 : "=r"(r0), "=r"(r1), "=r"(r2), "=r"(r3) : "r"(addr))

__device__ __forceinline__ unsigned pack_hi(float x0, float x1, float& r0, float& r1) {
    __nv_bfloat16 h0 = __float2bfloat16_rn(x0);
    __nv_bfloat16 h1 = __float2bfloat16_rn(x1);
    r0 = x0 - __bfloat162float(h0);
    r1 = x1 - __bfloat162float(h1);
    __nv_bfloat162 hp = __halves2bfloat162(h0, h1);   // low = even k
    return *(unsigned*)&hp;
}
__device__ __forceinline__ unsigned pack_lo(float r0, float r1) {
    __nv_bfloat162 lp = __halves2bfloat162(__float2bfloat16_rn(r0), __float2bfloat16_rn(r1));
    return *(unsigned*)&lp;
}

// split 8 consecutive fp32 into hi/lo bf16 pair-packed words
__device__ __forceinline__ void split2_pack(const float* v, unsigned* hi, unsigned* lo) {
    #pragma unroll
    for (int i = 0; i < 4; i++) {
        float r0, r1;
        hi[i] = pack_hi(v[2*i], v[2*i+1], r0, r1);
        lo[i] = pack_lo(r0, r1);
    }
}

// ---------------- weight prepack: W[N,K] -> fragment-ordered bf16 hi/lo ----------------
// out[(nb*KT + kt)*32 + lane] = {b0hi, b1hi, b0lo, b1lo}
// b0 = pack(W[nb*8+g][kt*16+2*t4], W[..][+1]); b1 = same at k+8.
__global__ void prepack_kernel(const float* __restrict__ W, uint4* __restrict__ out,
                               int K, int KT, int total) {
    int idx = blockIdx.x * 256 + threadIdx.x;
    if (idx >= total) return;
    int lane = idx & 31;
    int rest = idx >> 5;
    int kt = rest % KT;
    int nb = rest / KT;
    int g = lane >> 2, t4 = lane & 3;
    const float* row = W + (size_t)(nb * 8 + g) * K + kt * 16;
    float x0 = row[2*t4], x1 = row[2*t4 + 1];
    float x2 = row[8 + 2*t4], x3 = row[8 + 2*t4 + 1];
    float r0, r1, r2, r3;
    unsigned b0h = pack_hi(x0, x1, r0, r1);
    unsigned b1h = pack_hi(x2, x3, r2, r3);
    unsigned b0l = pack_lo(r0, r1);
    unsigned b1l = pack_lo(r2, r3);
    out[idx] = make_uint4(b0h, b1h, b0l, b1l);
}

// ---------------- 3xBF16 tensor-core GEMM, A via smem/ldmatrix, B via packed LDG ----------------
// C[M,N] = A[M,K] @ W[N,K]^T. Block tile 128x128, Ktile=16, double-buffered A,
// ONE sync per K-tile. 8 warps in 2(m) x 4(n), warp tile 64x32.
// smem: per buffer 2 planes (Ahi, Alo), row-major [128][16]bf16, 48B row stride.
#define ROWSTRIDE_W 12
#define ROWSTRIDE_B 48
#define PLANE_W (128 * ROWSTRIDE_W)      // 1536 words
#define PLANE_B (PLANE_W * 4)            // 6144 bytes
#define BUF_W (2 * PLANE_W)              // 3072 words
#define BUF_B (BUF_W * 4)                // 12288 bytes
#define GEMM_SMEM_BYTES (2 * BUF_B)      // 24576 bytes

__device__ __forceinline__ void cvt_store_tileA(unsigned* buf, int word_off,
                                                const float4& av0, const float4& av1) {
    float va[8] = {av0.x, av0.y, av0.z, av0.w, av1.x, av1.y, av1.z, av1.w};
    unsigned ahi[4], alo[4];
    split2_pack(va, ahi, alo);
    *(uint4*)(buf + word_off)           = make_uint4(ahi[0], ahi[1], ahi[2], ahi[3]);
    *(uint4*)(buf + PLANE_W + word_off) = make_uint4(alo[0], alo[1], alo[2], alo[3]);
}

template <bool GELU>
__global__ __launch_bounds__(256, 2)
void mp_gemm(const float* __restrict__ A, const uint4* __restrict__ Wp,
             const float* __restrict__ bias, const float* __restrict__ res,
             float* __restrict__ C, int M, int N, int K) {
    extern __shared__ unsigned sm[];
    unsigned sbase = (unsigned)__cvta_generic_to_shared(sm);

    int t = threadIdx.x;
    int warp = t >> 5, lane = t & 31;
    int g = lane >> 2, t4 = lane & 3;
    int wm = (warp >> 2) * 64;   // warp m-offset
    int wn = (warp & 3) * 32;    // warp n-offset
    int bx = blockIdx.x, by = blockIdx.y;
    int KT = K >> 4;

    // loader mapping: thread owns 8 consecutive k of one row
    int lrow = t & 127;
    int half = t >> 7;
    const float* Ag = A + (size_t)(by * 128 + lrow) * K + half * 8;
    int st_off = lrow * ROWSTRIDE_W + half * 4;

    // A ldmatrix per-lane byte offset (within a plane)
    unsigned a_off = (unsigned)((wm + (lane & 7) + ((lane >> 3) & 1) * 8) * ROWSTRIDE_B
                                + (lane >> 4) * 16);

    // packed-weight pointers per nt (stride between tiles = 32 uint4)
    const uint4* wp[4];
    #pragma unroll
    for (int nt = 0; nt < 4; nt++) {
        int nbg = bx * 16 + (wn >> 3) + nt;
        wp[nt] = Wp + ((size_t)nbg * KT) * 32 + lane;
    }

    float acc[4][4][4];
    #pragma unroll
    for (int i = 0; i < 4; i++)
        #pragma unroll
        for (int j = 0; j < 4; j++)
            #pragma unroll
            for (int c = 0; c < 4; c++) acc[i][j][c] = 0.0f;

    // prologue: tile 0 -> buffer 0
    float4 av0 = *(const float4*)(Ag);
    float4 av1 = *(const float4*)(Ag + 4);
    cvt_store_tileA(sm, st_off, av0, av1);
    __syncthreads();

    int ntiles = KT;
    int buf = 0;
    for (int it = 0; it < ntiles; it++) {
        bool more = (it + 1 < ntiles);

        // B fragments for this tile: 4 coalesced LDG.128 (L1/L2-hot weights)
        uint4 wq[4];
        #pragma unroll
        for (int nt = 0; nt < 4; nt++) wq[nt] = wp[nt][(size_t)it * 32];

        // global prefetch of next A tile (latency hidden under mma)
        if (more) {
            int kn = (it + 1) << 4;
            av0 = *(const float4*)(Ag + kn);
            av1 = *(const float4*)(Ag + kn + 4);
        }

        unsigned ab = sbase + buf * BUF_B;
        unsigned ah[4][4], al[4][4];
        #pragma unroll
        for (int mt = 0; mt < 4; mt++) {
            unsigned ad = ab + a_off + mt * (16 * ROWSTRIDE_B);
            LDSM4(ah[mt][0], ah[mt][1], ah[mt][2], ah[mt][3], ad);
            LDSM4(al[mt][0], al[mt][1], al[mt][2], al[mt][3], ad + PLANE_B);
        }

        #pragma unroll
        for (int nt = 0; nt < 4; nt++) {
            unsigned bfh[2] = {wq[nt].x, wq[nt].y};
            unsigned bfl[2] = {wq[nt].z, wq[nt].w};
            #pragma unroll
            for (int mt = 0; mt < 4; mt++) {
                mma_bf16(acc[mt][nt], ah[mt], bfh);
                mma_bf16(acc[mt][nt], ah[mt], bfl);
                mma_bf16(acc[mt][nt], al[mt], bfh);
            }
        }

        // convert + store next A tile into the other buffer, then single barrier
        if (more) {
            cvt_store_tileA(sm + (buf ^ 1) * BUF_W, st_off, av0, av1);
            __syncthreads();
        }
        buf ^= 1;
    }

    // epilogue: c0,c1 -> (row, col..col+1); c2,c3 -> (row+8, col..col+1)
    #pragma unroll
    for (int mt = 0; mt < 4; mt++) {
        int row0 = by * 128 + wm + mt * 16 + g;
        #pragma unroll
        for (int nt = 0; nt < 4; nt++) {
            int col = bx * 128 + wn + nt * 8 + t4 * 2;
            float bx0 = 0.0f, bx1 = 0.0f;
            if (bias) { bx0 = bias[col]; bx1 = bias[col + 1]; }
            #pragma unroll
            for (int hh = 0; hh < 2; hh++) {
                int row = row0 + hh * 8;
                float v0 = acc[mt][nt][hh * 2 + 0] + bx0;
                float v1 = acc[mt][nt][hh * 2 + 1] + bx1;
                if (GELU) { v0 = gelu_f(v0); v1 = gelu_f(v1); }
                size_t off = (size_t)row * N + col;
                if (res) {
                    float2 rv = *(const float2*)(res + off);
                    v0 += rv.x; v1 += rv.y;
                }
                *(float2*)(C + off) = make_float2(v0, v1);
            }
        }
    }
}

// ---------------- windowed attention: one block per (batch, window, head) ----------------
__global__ __launch_bounds__(256)
void attn_kernel(const float* __restrict__ qkv, float* __restrict__ out) {
    __shared__ float Qs[64][36], Ks[64][36], Vs[64][36];
    __shared__ float Ps[64][65];
    int blk = blockIdx.x;
    int h = blk & 7, wwin = (blk >> 3) & 15, b = blk >> 7;
    int base = b * 1024 + wwin * 64;
    int t = threadIdx.x;

    for (int i = t; i < 512; i += 256) {
        int row = i >> 3, dg = (i & 7) * 4;
        const float* src = qkv + (size_t)(base + row) * QKVD + h * 32 + dg;
        float4 q4 = *(const float4*)(src);
        float4 k4 = *(const float4*)(src + 256);
        float4 v4 = *(const float4*)(src + 512);
        *(float4*)&Qs[row][dg] = q4;
        *(float4*)&Ks[row][dg] = k4;
        *(float4*)&Vs[row][dg] = v4;
    }
    __syncthreads();

    int qt  = (t >> 4) * 4;
    int kt4 = (t & 15) * 4;
    float s[4][4];
    #pragma unroll
    for (int i = 0; i < 4; i++)
        #pragma unroll
        for (int j = 0; j < 4; j++) s[i][j] = 0.0f;

    #pragma unroll
    for (int d = 0; d < 32; d += 4) {
        float4 qv[4], kv[4];
        #pragma unroll
        for (int i = 0; i < 4; i++) qv[i] = *(const float4*)&Qs[qt + i][d];
        #pragma unroll
        for (int j = 0; j < 4; j++) kv[j] = *(const float4*)&Ks[kt4 + j][d];
        #pragma unroll
        for (int i = 0; i < 4; i++)
            #pragma unroll
            for (int j = 0; j < 4; j++)
                s[i][j] += qv[i].x * kv[j].x + qv[i].y * kv[j].y +
                           qv[i].z * kv[j].z + qv[i].w * kv[j].w;
    }
    const float scale = 0.17677669529663687f;  // 1/sqrt(32)
    #pragma unroll
    for (int i = 0; i < 4; i++) {
        #pragma unroll
        for (int j = 0; j < 4; j++) s[i][j] *= scale;
        float m = fmaxf(fmaxf(s[i][0], s[i][1]), fmaxf(s[i][2], s[i][3]));
        #pragma unroll
        for (int off = 8; off >= 1; off >>= 1)
            m = fmaxf(m, __shfl_xor_sync(0xffffffffu, m, off));
        float sum = 0.0f;
        #pragma unroll
        for (int j = 0; j < 4; j++) { s[i][j] = expf(s[i][j] - m); sum += s[i][j]; }
        #pragma unroll
        for (int off = 8; off >= 1; off >>= 1)
            sum += __shfl_xor_sync(0xffffffffu, sum, off);
        float inv = 1.0f / sum;
        #pragma unroll
        for (int j = 0; j < 4; j++) Ps[qt + i][kt4 + j] = s[i][j] * inv;
    }
    __syncthreads();

    int q = t >> 2, d0 = (t & 3) * 8;
    float acc[8];
    #pragma unroll
    for (int j = 0; j < 8; j++) acc[j] = 0.0f;
    #pragma unroll 4
    for (int k = 0; k < 64; k++) {
        float p = Ps[q][k];
        float4 v0 = *(const float4*)&Vs[k][d0];
        float4 v1 = *(const float4*)&Vs[k][d0 + 4];
        acc[0] += p * v0.x; acc[1] += p * v0.y; acc[2] += p * v0.z; acc[3] += p * v0.w;
        acc[4] += p * v1.x; acc[5] += p * v1.y; acc[6] += p * v1.z; acc[7] += p * v1.w;
    }
    float* dst = out + (size_t)(base + q) * DMODEL + h * 32 + d0;
    *(float4*)(dst)     = make_float4(acc[0], acc[1], acc[2], acc[3]);
    *(float4*)(dst + 4) = make_float4(acc[4], acc[5], acc[6], acc[7]);
}

// ---------------- launch ----------------
extern "C" void kernel_launch(void* const* d_in, const int* in_sizes, int n_in,
                              void* d_out, int out_size) {
    (void)in_sizes; (void)n_in; (void)out_size;
    const float* x      = (const float*)d_in[0];
    const float* conv_w = (const float*)d_in[1];
    const float* conv_b = (const float*)d_in[2];
    const float* ln_w   = (const float*)d_in[3];
    const float* ln_b   = (const float*)d_in[4];
    const float* qkv_w  = (const float*)d_in[5];
    const float* qkv_b  = (const float*)d_in[6];
    const float* proj_w = (const float*)d_in[7];
    const float* proj_b = (const float*)d_in[8];
    const float* ff_w1  = (const float*)d_in[9];
    const float* ff_b1  = (const float*)d_in[10];
    const float* ff_w2  = (const float*)d_in[11];
    const float* ff_b2  = (const float*)d_in[12];
    float* out = (float*)d_out;

    float *patches, *pre, *h0, *hid, *tmp, *qkvp, *h2;
    uint4* wpool;
    cudaGetSymbolAddress((void**)&patches, g_patches);
    cudaGetSymbolAddress((void**)&pre,     g_pre);
    cudaGetSymbolAddress((void**)&h0,      g_h0);
    cudaGetSymbolAddress((void**)&hid,     g_hid);
    cudaGetSymbolAddress((void**)&tmp,     g_tmp);
    cudaGetSymbolAddress((void**)&qkvp,    g_qkv);
    cudaGetSymbolAddress((void**)&h2,      g_h2);
    cudaGetSymbolAddress((void**)&wpool,   g_wpool);

    // 0) weight prepack (tiny; overlaps nothing but costs ~10us total)
    prepack_kernel<<<(256*768/4 + 255)/256, 256>>>(conv_w, wpool + OFF_CONV, 768, 48, 256*768/4);
    prepack_kernel<<<(768*256/4 + 255)/256, 256>>>(qkv_w,  wpool + OFF_QKV,  256, 16, 768*256/4);
    prepack_kernel<<<(256*256/4 + 255)/256, 256>>>(proj_w, wpool + OFF_PROJ, 256, 16, 256*256/4);
    prepack_kernel<<<(1024*256/4 + 255)/256, 256>>>(ff_w1, wpool + OFF_FF1,  256, 16, 1024*256/4);
    prepack_kernel<<<(256*1024/4 + 255)/256, 256>>>(ff_w2, wpool + OFF_FF2, 1024, 64, 256*1024/4);

    // 1) patch extraction + embed GEMM + LN + PE
    im2col_kernel<<<24576, 256>>>(x);
    mp_gemm<false><<<dim3(2, 256), 256, GEMM_SMEM_BYTES>>>(patches, wpool + OFF_CONV, conv_b, nullptr, pre, TOK, DMODEL, PK);
    ln_pe_kernel<<<4096, 256>>>(ln_w, ln_b);

    // 2) FFN #1
    mp_gemm<true ><<<dim3(8, 256), 256, GEMM_SMEM_BYTES>>>(h0,  wpool + OFF_FF1, ff_b1, nullptr, hid, TOK, HFF, DMODEL);
    mp_gemm<false><<<dim3(2, 256), 256, GEMM_SMEM_BYTES>>>(hid, wpool + OFF_FF2, ff_b2, nullptr, tmp, TOK, DMODEL, HFF);

    // 3) windowed attention (qkv -> attn -> proj + residual(h0))
    mp_gemm<false><<<dim3(6, 256), 256, GEMM_SMEM_BYTES>>>(tmp, wpool + OFF_QKV, qkv_b, nullptr, qkvp, TOK, QKVD, DMODEL);
    attn_kernel<<<4096, 256>>>(qkvp, tmp);
    mp_gemm<false><<<dim3(2, 256), 256, GEMM_SMEM_BYTES>>>(tmp, wpool + OFF_PROJ, proj_b, h0, h2, TOK, DMODEL, DMODEL);

    // 4) FFN #2 + residual(h2) -> d_out
    mp_gemm<true ><<<dim3(8, 256), 256, GEMM_SMEM_BYTES>>>(h2,  wpool + OFF_FF1, ff_b1, nullptr, hid, TOK, HFF, DMODEL);
    mp_gemm<false><<<dim3(2, 256), 256, GEMM_SMEM_BYTES>>>(hid, wpool + OFF_FF2, ff_b2, h2, out, TOK, DMODEL, HFF);
}

// round 11
// speedup vs baseline: 1.5124x; 1.2621x over previous
#include <cuda_runtime.h>
#include <cuda_bf16.h>
#include <math.h>

#define TOK 32768
#define DMODEL 256
#define HFF 1024
#define QKVD 768
#define PK 768

// ============ packed format: per (rowblk128, ktile16): 8KB block ============
// hi plane 4KB: byte = SW(row*32 + (k&15)*2); lo plane at +4096.
#define SW(b) ((b) ^ (((b) >> 3) & 0x70))

__device__ float    g_pre[TOK * DMODEL];
__device__ float    g_h0 [TOK * DMODEL];
__device__ float    g_qkv[TOK * QKVD];
__device__ float    g_h2 [TOK * DMODEL];

__device__ unsigned gp_patches[TOK * PK];   // packed, KT=48
__device__ unsigned gp_h0 [TOK * DMODEL];   // packed, KT=16
__device__ unsigned gp_hid[TOK * HFF];      // packed, KT=64
__device__ unsigned gp_tmp[TOK * DMODEL];   // packed, KT=16

// packed weights (word offsets)
#define WOFF_CONV 0
#define WOFF_QKV  196608
#define WOFF_PROJ 393216
#define WOFF_FF1  458752
#define WOFF_FF2  720896
__device__ unsigned g_wpool[983040];

// ============ helpers ============
__device__ __forceinline__ float gelu_f(float x) {
    return 0.5f * x * (1.0f + tanhf(0.7978845608028654f * (x + 0.044715f * x * x * x)));
}
__device__ __forceinline__ unsigned pack_hi(float x0, float x1, float& r0, float& r1) {
    __nv_bfloat16 h0 = __float2bfloat16_rn(x0);
    __nv_bfloat16 h1 = __float2bfloat16_rn(x1);
    r0 = x0 - __bfloat162float(h0);
    r1 = x1 - __bfloat162float(h1);
    __nv_bfloat162 hp = __halves2bfloat162(h0, h1);   // low half = even k
    return *(unsigned*)&hp;
}
__device__ __forceinline__ unsigned pack_lo(float r0, float r1) {
    __nv_bfloat162 lp = __halves2bfloat162(__float2bfloat16_rn(r0), __float2bfloat16_rn(r1));
    return *(unsigned*)&lp;
}
__device__ __forceinline__ unsigned smem_u32(const void* p) {
    unsigned a;
    asm("{ .reg .u64 t; cvta.to.shared.u64 t, %1; cvt.u32.u64 %0, t; }" : "=r"(a) : "l"(p));
    return a;
}

__device__ __forceinline__ void mma_bf16(float* d, const unsigned* a, const unsigned* b) {
    asm volatile(
        "mma.sync.aligned.m16n8k16.row.col.f32.bf16.bf16.f32 "
        "{%0,%1,%2,%3}, {%4,%5,%6,%7}, {%8,%9}, {%0,%1,%2,%3};\n"
        : "+f"(d[0]), "+f"(d[1]), "+f"(d[2]), "+f"(d[3])
        : "r"(a[0]), "r"(a[1]), "r"(a[2]), "r"(a[3]), "r"(b[0]), "r"(b[1]));
}
#define LDSM4(r0, r1, r2, r3, addr) \
    asm volatile("ldmatrix.sync.aligned.m8n8.x4.shared.b16 {%0,%1,%2,%3}, [%4];" \
                 : "=r"(r0), "=r"(r1), "=r"(r2), "=r"(r3) : "r"(addr))

// mbarrier + bulk copy (compile-verified on this harness in R9)
#define MBAR_INIT(addr, cnt) \
    asm volatile("mbarrier.init.shared.b64 [%0], %1;" :: "r"(addr), "r"(cnt) : "memory")
#define MBAR_EXPECT_TX(addr, bytes) \
    asm volatile("mbarrier.arrive.expect_tx.shared.b64 _, [%0], %1;" :: "r"(addr), "r"(bytes) : "memory")
#define MBAR_ARRIVE(addr) \
    asm volatile("mbarrier.arrive.shared.b64 _, [%0];" :: "r"(addr) : "memory")
#define MBAR_WAIT(addr, par) do {                                              \
    asm volatile("{\n\t.reg .pred P1;\n\t"                                     \
        "WL_%=:\n\t"                                                           \
        "mbarrier.try_wait.parity.acquire.cta.shared::cta.b64 P1, [%0], %1, 0x989680;\n\t" \
        "@P1 bra.uni WD_%=;\n\t"                                               \
        "bra.uni WL_%=;\n\t"                                                   \
        "WD_%=:\n\t}"                                                          \
        :: "r"(addr), "r"(par) : "memory");                                    \
} while (0)
#define BULK_CP(dst, src, bytes, mbar) \
    asm volatile("cp.async.bulk.shared::cluster.global.mbarrier::complete_tx::bytes [%0], [%1], %2, [%3];" \
                 :: "r"(dst), "l"(src), "r"(bytes), "r"(mbar) : "memory")

// ============ im2col -> packed patches ============
__global__ void im2col_kernel(const float* __restrict__ x) {
    int idx = blockIdx.x * blockDim.x + threadIdx.x;
    int tok = idx / 192;
    int p4  = (idx % 192) * 4;
    int b = tok >> 10;
    int n = tok & 1023;
    int ph = n >> 5, pw = n & 31;
    int c = p4 >> 8;
    int r = p4 & 255;
    int py = r >> 4, px = r & 15;
    const float* src = x + (((size_t)(b * 3 + c) * 512 + ph * 16 + py) * 512 + pw * 16 + px);
    float4 v = *(const float4*)src;
    int row = tok & 127, mb = tok >> 7;
    int kt = p4 >> 4, kloc = p4 & 15;
    unsigned w = SW((unsigned)(row * 32 + kloc * 2));
    unsigned* obk = gp_patches + ((size_t)mb * 48 + kt) * 2048 + (w >> 2);
    float r0, r1;
    unsigned h0 = pack_hi(v.x, v.y, r0, r1);
    unsigned l0 = pack_lo(r0, r1);
    unsigned h1 = pack_hi(v.z, v.w, r0, r1);
    unsigned l1 = pack_lo(r0, r1);
    *(uint2*)obk          = make_uint2(h0, h1);
    *(uint2*)(obk + 1024) = make_uint2(l0, l1);
}

// ============ LN + PE (fp32 h0 + packed h0) ============
__global__ void ln_pe_kernel(const float* __restrict__ w, const float* __restrict__ b) {
    int gt = blockIdx.x * 8 + (threadIdx.x >> 5);
    int lane = threadIdx.x & 31;
    const float4* row = (const float4*)(g_pre + (size_t)gt * DMODEL);
    float4 v0 = row[lane];
    float4 v1 = row[lane + 32];
    float s  = v0.x + v0.y + v0.z + v0.w + v1.x + v1.y + v1.z + v1.w;
    float ss = v0.x*v0.x + v0.y*v0.y + v0.z*v0.z + v0.w*v0.w
             + v1.x*v1.x + v1.y*v1.y + v1.z*v1.z + v1.w*v1.w;
    #pragma unroll
    for (int off = 16; off >= 1; off >>= 1) {
        s  += __shfl_xor_sync(0xffffffffu, s, off);
        ss += __shfl_xor_sync(0xffffffffu, ss, off);
    }
    float mean = s * (1.0f / 256.0f);
    float var  = ss * (1.0f / 256.0f) - mean * mean;
    float rstd = rsqrtf(var + 1e-5f);
    int n = gt & 1023;
    float nf = (float)n;

    float4 wv0 = ((const float4*)w)[lane];
    float4 wv1 = ((const float4*)w)[lane + 32];
    float4 bv0 = ((const float4*)b)[lane];
    float4 bv1 = ((const float4*)b)[lane + 32];

    float o[8];
    int d0 = lane * 4;
    const float C = -9.210340371976184f / 256.0f;
    float xv[8] = {v0.x, v0.y, v0.z, v0.w, v1.x, v1.y, v1.z, v1.w};
    float wv[8] = {wv0.x, wv0.y, wv0.z, wv0.w, wv1.x, wv1.y, wv1.z, wv1.w};
    float bb[8] = {bv0.x, bv0.y, bv0.z, bv0.w, bv1.x, bv1.y, bv1.z, bv1.w};
    #pragma unroll
    for (int i = 0; i < 8; i++) {
        int d = (i < 4) ? (d0 + i) : (128 + d0 + (i - 4));
        float ang = nf * expf(C * (float)(d & ~1));
        float pe = (d & 1) ? cosf(ang) : sinf(ang);
        o[i] = (xv[i] - mean) * rstd * wv[i] + bb[i] + pe;
    }
    float4* orow = (float4*)(g_h0 + (size_t)gt * DMODEL);
    orow[lane]      = make_float4(o[0], o[1], o[2], o[3]);
    orow[lane + 32] = make_float4(o[4], o[5], o[6], o[7]);

    int prow = gt & 127, mb = gt >> 7;
    #pragma unroll
    for (int half = 0; half < 2; half++) {
        int d = half * 128 + d0;
        int kt = d >> 4, kloc = d & 15;
        unsigned wsw = SW((unsigned)(prow * 32 + kloc * 2));
        unsigned* obk = gp_h0 + ((size_t)mb * 16 + kt) * 2048 + (wsw >> 2);
        float r0, r1;
        unsigned h0w = pack_hi(o[half*4+0], o[half*4+1], r0, r1);
        unsigned l0w = pack_lo(r0, r1);
        unsigned h1w = pack_hi(o[half*4+2], o[half*4+3], r0, r1);
        unsigned l1w = pack_lo(r0, r1);
        *(uint2*)obk          = make_uint2(h0w, h1w);
        *(uint2*)(obk + 1024) = make_uint2(l0w, l1w);
    }
}

// ============ weight prepack ============
__global__ void prepack_kernel(const float* __restrict__ W, unsigned* __restrict__ out,
                               int K, int KT, int total_pairs) {
    int idx = blockIdx.x * 256 + threadIdx.x;
    if (idx >= total_pairs) return;
    int kh = K >> 1;
    int nrow = idx / kh;
    int k = (idx - nrow * kh) * 2;
    int nb = nrow >> 7, row = nrow & 127;
    int kt = k >> 4, kloc = k & 15;
    float x0 = W[(size_t)nrow * K + k];
    float x1 = W[(size_t)nrow * K + k + 1];
    float r0, r1;
    unsigned hw = pack_hi(x0, x1, r0, r1);
    unsigned lw = pack_lo(r0, r1);
    unsigned wsw = SW((unsigned)(row * 32 + kloc * 2));
    unsigned* obk = out + ((size_t)nb * KT + kt) * 2048 + (wsw >> 2);
    obk[0]    = hw;
    obk[1024] = lw;
}

// ============ GEMM: mma.sync + bulk-copy pipeline ============
// CTA 128 thr (4 warps 2m x 2n), CTA tile 128x128, warp 64x64, k-tile 16,
// 4-stage pipeline: stage = [A 8KB][B 8KB], mbarrier full/empty, no syncthreads.
#define STAGE_BYTES 16384
#define GEMM_SMEM_BYTES (4 * STAGE_BYTES + 1024)

template <bool GELU, bool RES, bool WF32, bool WPACK>
__global__ __launch_bounds__(128, 2)
void mp_gemm(const char* __restrict__ Ap, const char* __restrict__ Bp,
             const float* __restrict__ bias, const float* __restrict__ res,
             float* __restrict__ Cf, unsigned* __restrict__ Cp,
             int Nn, int K, int KTP) {
    extern __shared__ char dynsm[];
    __shared__ __align__(8) unsigned long long bars[8];   // full[4], empty[4]
    unsigned sbase  = (smem_u32(dynsm) + 1023u) & ~1023u;
    unsigned fullb  = smem_u32(&bars[0]);
    unsigned emptyb = smem_u32(&bars[4]);

    int tid = threadIdx.x, warp = tid >> 5, lane = tid & 31;
    int wm = (warp >> 1) * 64, wn = (warp & 1) * 64;
    int bx = blockIdx.x, by = blockIdx.y;
    int KT = K >> 4;

    if (tid == 0) {
        #pragma unroll
        for (int s = 0; s < 4; s++) {
            MBAR_INIT(fullb + s * 8, 1);
            MBAR_INIT(emptyb + s * 8, 128);
        }
    }
    __syncthreads();

    const char* Asrc = Ap + (size_t)by * KT * 8192;
    const char* Bsrc = Bp + (size_t)bx * KT * 8192;

    if (tid == 0) {
        #pragma unroll
        for (int s = 0; s < 4; s++) {
            MBAR_EXPECT_TX(fullb + s * 8, 16384u);
            BULK_CP(sbase + s * 16384,        Asrc + (size_t)s * 8192, 8192u, fullb + s * 8);
            BULK_CP(sbase + s * 16384 + 8192, Bsrc + (size_t)s * 8192, 8192u, fullb + s * 8);
        }
    }

    // ldmatrix lane offsets (within 4KB plane; swizzle baked since bases are 1KB-aligned)
    int arow = wm + (lane & 7) + ((lane >> 3) & 1) * 8;
    unsigned aoff[4], boff[4];
    #pragma unroll
    for (int mt = 0; mt < 4; mt++) {
        unsigned bb = (unsigned)((arow + mt * 16) * 32 + (lane >> 4) * 16);
        aoff[mt] = SW(bb);
    }
    int brow = (lane & 7) + ((lane >> 4) & 1) * 8;
    #pragma unroll
    for (int p = 0; p < 4; p++) {
        unsigned bb = (unsigned)((wn + p * 16 + brow) * 32 + ((lane >> 3) & 1) * 16);
        boff[p] = SW(bb);
    }

    float acc[4][8][4];
    #pragma unroll
    for (int i = 0; i < 4; i++)
        #pragma unroll
        for (int j = 0; j < 8; j++)
            #pragma unroll
            for (int c = 0; c < 4; c++) acc[i][j][c] = 0.0f;

    for (int it = 0; it < KT; it++) {
        int s = it & 3;
        unsigned par = (unsigned)((it >> 2) & 1);
        MBAR_WAIT(fullb + s * 8, par);
        unsigned ab = sbase + s * 16384;

        unsigned ah[4][4], al[4][4], bh[4][4], bl[4][4];
        #pragma unroll
        for (int mt = 0; mt < 4; mt++) {
            LDSM4(ah[mt][0], ah[mt][1], ah[mt][2], ah[mt][3], ab + aoff[mt]);
            LDSM4(al[mt][0], al[mt][1], al[mt][2], al[mt][3], ab + 4096 + aoff[mt]);
        }
        #pragma unroll
        for (int p = 0; p < 4; p++) {
            LDSM4(bh[p][0], bh[p][1], bh[p][2], bh[p][3], ab + 8192 + boff[p]);
            LDSM4(bl[p][0], bl[p][1], bl[p][2], bl[p][3], ab + 12288 + boff[p]);
        }
        MBAR_ARRIVE(emptyb + s * 8);

        // refill this stage (producer thread; other warps proceed into mma)
        if (tid == 0 && it + 4 < KT) {
            MBAR_WAIT(emptyb + s * 8, par);
            MBAR_EXPECT_TX(fullb + s * 8, 16384u);
            BULK_CP(ab,        Asrc + (size_t)(it + 4) * 8192, 8192u, fullb + s * 8);
            BULK_CP(ab + 8192, Bsrc + (size_t)(it + 4) * 8192, 8192u, fullb + s * 8);
        }

        #pragma unroll
        for (int mt = 0; mt < 4; mt++)
            #pragma unroll
            for (int j = 0; j < 8; j++) {
                int p = j >> 1, q = (j & 1) * 2;
                unsigned bfh[2] = {bh[p][q], bh[p][q + 1]};
                unsigned bfl[2] = {bl[p][q], bl[p][q + 1]};
                mma_bf16(acc[mt][j], ah[mt], bfh);
                mma_bf16(acc[mt][j], ah[mt], bfl);
                mma_bf16(acc[mt][j], al[mt], bfh);
            }
    }

    // epilogue
    int g = lane >> 2, t4 = lane & 3;
    #pragma unroll
    for (int mt = 0; mt < 4; mt++) {
        int lrow0 = wm + mt * 16 + g;
        #pragma unroll
        for (int j = 0; j < 8; j++) {
            int colg = bx * 128 + wn + j * 8 + t4 * 2;
            float2 b2 = *(const float2*)(bias + colg);
            #pragma unroll
            for (int h = 0; h < 2; h++) {
                int lrow = lrow0 + h * 8;
                int grow = by * 128 + lrow;
                float v0 = acc[mt][j][h * 2 + 0] + b2.x;
                float v1 = acc[mt][j][h * 2 + 1] + b2.y;
                if (GELU) { v0 = gelu_f(v0); v1 = gelu_f(v1); }
                if (RES) {
                    float2 rv = *(const float2*)(res + (size_t)grow * Nn + colg);
                    v0 += rv.x; v1 += rv.y;
                }
                if (WF32)
                    *(float2*)(Cf + (size_t)grow * Nn + colg) = make_float2(v0, v1);
                if (WPACK) {
                    int ktp = colg >> 4, kloc = colg & 15;
                    unsigned wsw = SW((unsigned)(lrow * 32 + kloc * 2));
                    unsigned* obk = Cp + ((size_t)by * KTP + ktp) * 2048 + (wsw >> 2);
                    float r0, r1;
                    unsigned hw = pack_hi(v0, v1, r0, r1);
                    obk[0]    = hw;
                    obk[1024] = pack_lo(r0, r1);
                }
            }
        }
    }
}

// ============ windowed attention (fp32 in, packed out) ============
__global__ __launch_bounds__(256)
void attn_kernel(const float* __restrict__ qkv) {
    __shared__ float Qs[64][36], Ks[64][36], Vs[64][36];
    __shared__ float Ps[64][65];
    int blk = blockIdx.x;
    int h = blk & 7, wwin = (blk >> 3) & 15, b = blk >> 7;
    int base = b * 1024 + wwin * 64;
    int t = threadIdx.x;

    for (int i = t; i < 512; i += 256) {
        int row = i >> 3, dg = (i & 7) * 4;
        const float* src = qkv + (size_t)(base + row) * QKVD + h * 32 + dg;
        *(float4*)&Qs[row][dg] = *(const float4*)(src);
        *(float4*)&Ks[row][dg] = *(const float4*)(src + 256);
        *(float4*)&Vs[row][dg] = *(const float4*)(src + 512);
    }
    __syncthreads();

    int qt  = (t >> 4) * 4;
    int kt4 = (t & 15) * 4;
    float s[4][4];
    #pragma unroll
    for (int i = 0; i < 4; i++)
        #pragma unroll
        for (int j = 0; j < 4; j++) s[i][j] = 0.0f;

    #pragma unroll
    for (int d = 0; d < 32; d += 4) {
        float4 qv[4], kv[4];
        #pragma unroll
        for (int i = 0; i < 4; i++) qv[i] = *(const float4*)&Qs[qt + i][d];
        #pragma unroll
        for (int j = 0; j < 4; j++) kv[j] = *(const float4*)&Ks[kt4 + j][d];
        #pragma unroll
        for (int i = 0; i < 4; i++)
            #pragma unroll
            for (int j = 0; j < 4; j++)
                s[i][j] += qv[i].x * kv[j].x + qv[i].y * kv[j].y +
                           qv[i].z * kv[j].z + qv[i].w * kv[j].w;
    }
    const float scale = 0.17677669529663687f;
    #pragma unroll
    for (int i = 0; i < 4; i++) {
        #pragma unroll
        for (int j = 0; j < 4; j++) s[i][j] *= scale;
        float m = fmaxf(fmaxf(s[i][0], s[i][1]), fmaxf(s[i][2], s[i][3]));
        #pragma unroll
        for (int off = 8; off >= 1; off >>= 1)
            m = fmaxf(m, __shfl_xor_sync(0xffffffffu, m, off));
        float sum = 0.0f;
        #pragma unroll
        for (int j = 0; j < 4; j++) { s[i][j] = expf(s[i][j] - m); sum += s[i][j]; }
        #pragma unroll
        for (int off = 8; off >= 1; off >>= 1)
            sum += __shfl_xor_sync(0xffffffffu, sum, off);
        float inv = 1.0f / sum;
        #pragma unroll
        for (int j = 0; j < 4; j++) Ps[qt + i][kt4 + j] = s[i][j] * inv;
    }
    __syncthreads();

    int q = t >> 2, d0 = (t & 3) * 8;
    float acc[8];
    #pragma unroll
    for (int j = 0; j < 8; j++) acc[j] = 0.0f;
    #pragma unroll 4
    for (int k = 0; k < 64; k++) {
        float p = Ps[q][k];
        float4 v0 = *(const float4*)&Vs[k][d0];
        float4 v1 = *(const float4*)&Vs[k][d0 + 4];
        acc[0] += p * v0.x; acc[1] += p * v0.y; acc[2] += p * v0.z; acc[3] += p * v0.w;
        acc[4] += p * v1.x; acc[5] += p * v1.y; acc[6] += p * v1.z; acc[7] += p * v1.w;
    }
    int tok = base + q;
    int prow = tok & 127, mb = tok >> 7;
    int col0 = h * 32 + d0;
    int kt = col0 >> 4, kloc = col0 & 15;
    unsigned wsw = SW((unsigned)(prow * 32 + kloc * 2));
    unsigned* obk = gp_tmp + ((size_t)mb * 16 + kt) * 2048 + (wsw >> 2);
    unsigned hw[4], lw[4];
    #pragma unroll
    for (int j = 0; j < 4; j++) {
        float r0, r1;
        hw[j] = pack_hi(acc[2 * j], acc[2 * j + 1], r0, r1);
        lw[j] = pack_lo(r0, r1);
    }
    *(uint4*)obk          = make_uint4(hw[0], hw[1], hw[2], hw[3]);
    *(uint4*)(obk + 1024) = make_uint4(lw[0], lw[1], lw[2], lw[3]);
}

// ============ launch ============
extern "C" void kernel_launch(void* const* d_in, const int* in_sizes, int n_in,
                              void* d_out, int out_size) {
    (void)in_sizes; (void)n_in; (void)out_size;
    const float* x      = (const float*)d_in[0];
    const float* conv_w = (const float*)d_in[1];
    const float* conv_b = (const float*)d_in[2];
    const float* ln_w   = (const float*)d_in[3];
    const float* ln_b   = (const float*)d_in[4];
    const float* qkv_w  = (const float*)d_in[5];
    const float* qkv_b  = (const float*)d_in[6];
    const float* proj_w = (const float*)d_in[7];
    const float* proj_b = (const float*)d_in[8];
    const float* ff_w1  = (const float*)d_in[9];
    const float* ff_b1  = (const float*)d_in[10];
    const float* ff_w2  = (const float*)d_in[11];
    const float* ff_b2  = (const float*)d_in[12];
    float* out = (float*)d_out;

    float *pre, *h0, *qkvf, *h2;
    unsigned *pp, *ph0, *phid, *ptmp, *wpool;
    cudaGetSymbolAddress((void**)&pre,   g_pre);
    cudaGetSymbolAddress((void**)&h0,    g_h0);
    cudaGetSymbolAddress((void**)&qkvf,  g_qkv);
    cudaGetSymbolAddress((void**)&h2,    g_h2);
    cudaGetSymbolAddress((void**)&pp,    gp_patches);
    cudaGetSymbolAddress((void**)&ph0,   gp_h0);
    cudaGetSymbolAddress((void**)&phid,  gp_hid);
    cudaGetSymbolAddress((void**)&ptmp,  gp_tmp);
    cudaGetSymbolAddress((void**)&wpool, g_wpool);

    static bool attr_done = false;
    if (!attr_done) {
        cudaFuncSetAttribute(mp_gemm<false,false,true ,false>, cudaFuncAttributeMaxDynamicSharedMemorySize, GEMM_SMEM_BYTES);
        cudaFuncSetAttribute(mp_gemm<true ,false,false,true >, cudaFuncAttributeMaxDynamicSharedMemorySize, GEMM_SMEM_BYTES);
        cudaFuncSetAttribute(mp_gemm<false,false,false,true >, cudaFuncAttributeMaxDynamicSharedMemorySize, GEMM_SMEM_BYTES);
        cudaFuncSetAttribute(mp_gemm<false,true ,true ,true >, cudaFuncAttributeMaxDynamicSharedMemorySize, GEMM_SMEM_BYTES);
        cudaFuncSetAttribute(mp_gemm<false,true ,true ,false>, cudaFuncAttributeMaxDynamicSharedMemorySize, GEMM_SMEM_BYTES);
        attr_done = true;
    }

    // 0) weight prepack (packed bf16 hi/lo blocks)
    prepack_kernel<<<(256*768/2 + 255)/256, 256>>>(conv_w, wpool + WOFF_CONV, 768, 48, 256*768/2);
    prepack_kernel<<<(768*256/2 + 255)/256, 256>>>(qkv_w,  wpool + WOFF_QKV,  256, 16, 768*256/2);
    prepack_kernel<<<(256*256/2 + 255)/256, 256>>>(proj_w, wpool + WOFF_PROJ, 256, 16, 256*256/2);
    prepack_kernel<<<(1024*256/2 + 255)/256, 256>>>(ff_w1, wpool + WOFF_FF1,  256, 16, 1024*256/2);
    prepack_kernel<<<(256*1024/2 + 255)/256, 256>>>(ff_w2, wpool + WOFF_FF2, 1024, 64, 256*1024/2);

    // 1) im2col (packed) -> embed GEMM (fp32 pre) -> LN+PE (fp32 h0 + packed)
    im2col_kernel<<<24576, 256>>>(x);
    mp_gemm<false,false,true ,false><<<dim3(2, 256), 128, GEMM_SMEM_BYTES>>>(
        (const char*)pp, (const char*)(wpool + WOFF_CONV), conv_b, nullptr, pre, nullptr, DMODEL, PK, 0);
    ln_pe_kernel<<<4096, 256>>>(ln_w, ln_b);

    // 2) FFN #1 (packed in/out)
    mp_gemm<true ,false,false,true ><<<dim3(8, 256), 128, GEMM_SMEM_BYTES>>>(
        (const char*)ph0, (const char*)(wpool + WOFF_FF1), ff_b1, nullptr, nullptr, phid, HFF, DMODEL, 64);
    mp_gemm<false,false,false,true ><<<dim3(2, 256), 128, GEMM_SMEM_BYTES>>>(
        (const char*)phid, (const char*)(wpool + WOFF_FF2), ff_b2, nullptr, nullptr, ptmp, DMODEL, HFF, 16);

    // 3) attention: qkv (fp32) -> attn (packed) -> proj (+res h0 -> fp32 h2 + packed)
    mp_gemm<false,false,true ,false><<<dim3(6, 256), 128, GEMM_SMEM_BYTES>>>(
        (const char*)ptmp, (const char*)(wpool + WOFF_QKV), qkv_b, nullptr, qkvf, nullptr, QKVD, DMODEL, 0);
    attn_kernel<<<4096, 256>>>(qkvf);
    mp_gemm<false,true ,true ,true ><<<dim3(2, 256), 128, GEMM_SMEM_BYTES>>>(
        (const char*)ptmp, (const char*)(wpool + WOFF_PROJ), proj_b, h0, h2, ph0, DMODEL, DMODEL, 16);

    // 4) FFN #2 (+res h2 -> d_out)
    mp_gemm<true ,false,false,true ><<<dim3(8, 256), 128, GEMM_SMEM_BYTES>>>(
        (const char*)ph0, (const char*)(wpool + WOFF_FF1), ff_b1, nullptr, nullptr, phid, HFF, DMODEL, 64);
    mp_gemm<false,true ,true ,false><<<dim3(2, 256), 128, GEMM_SMEM_BYTES>>>(
        (const char*)phid, (const char*)(wpool + WOFF_FF2), ff_b2, h2, out, nullptr, DMODEL, HFF, 0);
}